// round 7
// baseline (speedup 1.0000x reference)
#include <cuda_runtime.h>
#include <math.h>
#include <stdint.h>

#define N_NODES 50000
#define E_EDGES 800000
#define E_TOT   850000   // edges + self loops
#define HID 64
#define CLS 40

// ---------------- scratch (__device__ globals: allocation-free) ----------------
__device__ float g_h0[N_NODES * HID];
__device__ float g_h1[N_NODES * HID];
__device__ float g_ssrc[N_NODES];
__device__ float g_sdst[N_NODES];
__device__ int   g_cnt[N_NODES];      // zero-init; re-zeroed by k_offsets each call
__device__ int   g_off[N_NODES];
__device__ int   g_end[N_NODES];
__device__ int   g_cur[N_NODES];
__device__ int   g_csrc[E_TOT];
__device__ int   g_cursor;            // re-zeroed by k_hist each call

// ---------------- CSR build ----------------
__global__ void k_hist(const int* __restrict__ ei) {
    int i4 = blockIdx.x * blockDim.x + threadIdx.x;
    if (i4 == 0) g_cursor = 0;
    if (i4 < E_EDGES / 4) {
        int4 d = reinterpret_cast<const int4*>(ei + E_EDGES)[i4];
        if ((unsigned)d.x < N_NODES) atomicAdd(&g_cnt[d.x], 1);
        if ((unsigned)d.y < N_NODES) atomicAdd(&g_cnt[d.y], 1);
        if ((unsigned)d.z < N_NODES) atomicAdd(&g_cnt[d.z], 1);
        if ((unsigned)d.w < N_NODES) atomicAdd(&g_cnt[d.w], 1);
    }
}

__global__ void k_offsets() {
    int idx  = blockIdx.x * blockDim.x + threadIdx.x;
    int lane = threadIdx.x & 31;
    int v = 0;
    if (idx < N_NODES) { v = g_cnt[idx] + 1; g_cnt[idx] = 0; }  // +1 self loop; re-zero
    int incl = v;
    #pragma unroll
    for (int s = 1; s < 32; s <<= 1) {
        int t = __shfl_up_sync(0xffffffffu, incl, s);
        if (lane >= s) incl += t;
    }
    int tot = __shfl_sync(0xffffffffu, incl, 31);
    int base = 0;
    if (lane == 0) base = atomicAdd(&g_cursor, tot);
    base = __shfl_sync(0xffffffffu, base, 0);
    if (idx < N_NODES) {
        int excl = base + incl - v;
        g_off[idx] = excl;
        g_cur[idx] = excl;
        g_end[idx] = excl + v;
    }
}

__global__ void k_fill(const int* __restrict__ ei) {
    int i4 = blockIdx.x * blockDim.x + threadIdx.x;
    const int Q = E_EDGES / 4;
    if (i4 < Q) {
        int4 s = reinterpret_cast<const int4*>(ei)[i4];
        int4 d = reinterpret_cast<const int4*>(ei + E_EDGES)[i4];
        if ((unsigned)d.x < N_NODES && (unsigned)s.x < N_NODES) g_csrc[atomicAdd(&g_cur[d.x], 1)] = s.x;
        if ((unsigned)d.y < N_NODES && (unsigned)s.y < N_NODES) g_csrc[atomicAdd(&g_cur[d.y], 1)] = s.y;
        if ((unsigned)d.z < N_NODES && (unsigned)s.z < N_NODES) g_csrc[atomicAdd(&g_cur[d.z], 1)] = s.z;
        if ((unsigned)d.w < N_NODES && (unsigned)s.w < N_NODES) g_csrc[atomicAdd(&g_cur[d.w], 1)] = s.w;
    } else {
        int id = i4 - Q;
        if (id < N_NODES) g_csrc[atomicAdd(&g_cur[id], 1)] = id;  // self loop
    }
}

// ---------------- tf32x3 tensor-core GEMM ----------------
__device__ __forceinline__ uint32_t f2tf32(float x) {
    uint32_t r;
    asm("cvt.rna.tf32.f32 %0, %1;" : "=r"(r) : "f"(x));
    return r;
}

__device__ __forceinline__ void mma_tf32(float4& d,
                                         uint32_t a0, uint32_t a1, uint32_t a2, uint32_t a3,
                                         uint32_t b0, uint32_t b1) {
    asm volatile("mma.sync.aligned.m16n8k8.row.col.f32.tf32.tf32.f32 "
                 "{%0,%1,%2,%3}, {%4,%5,%6,%7}, {%8,%9}, {%0,%1,%2,%3};"
                 : "+f"(d.x), "+f"(d.y), "+f"(d.z), "+f"(d.w)
                 : "r"(a0), "r"(a1), "r"(a2), "r"(a3), "r"(b0), "r"(b1));
}

// H = X[Nx128-or-64] @ W[F x Ocols] (padded to 64 cols), plus fused s_src/s_dst dots.
// Block: 128 rows x 64 cols, 256 threads (8 warps, 32x32 per warp).
// A (X) staged 32 k at a time in mma-fragment order; split hi/lo in registers.
// B (W) staged once, pre-split hi/lo, fragment order: uint4 {b0h,b1h,b0l,b1l}.
template <int F>
__global__ void __launch_bounds__(256)
k_gemm_tc(const float* __restrict__ X, const float* __restrict__ W, int Ocols,
          const float* __restrict__ asrc, const float* __restrict__ adst,
          float* __restrict__ H) {
    extern __shared__ float sm[];
    uint4* Bs = reinterpret_cast<uint4*>(sm);     // F*32 uint4 = F*128 floats
    float* As = sm + F * 128;                     // 4096 floats (32k x 128m, frag order)
    float* sa = As + 4096;                        // 64
    float* sb = sa + 64;                          // 64
    float* sps = sb + 64;                         // 2*128
    float* spd = sps + 256;                       // 2*128

    const int tid  = threadIdx.x;
    const int lane = tid & 31;
    const int w    = tid >> 5;
    const int gid  = lane >> 2;
    const int tig  = lane & 3;
    const int mw   = (w & 3) * 2;    // first of this warp's two 16-row m-tiles
    const int nh   = w >> 2;         // n-half (0: cols 0-31, 1: cols 32-63)
    const int node0 = blockIdx.x * 128;

    if (tid < 64) {
        sa[tid] = (tid < Ocols) ? asrc[tid] : 0.f;
        sb[tid] = (tid < Ocols) ? adst[tid] : 0.f;
    }
    // stage B fragments (pre-split)
    for (int idx = tid; idx < F * 32; idx += 256) {
        int l  = idx & 31;
        int u  = (idx >> 5) & 7;      // ntile 0..7
        int ks = idx >> 8;            // kstep 0..F/8-1
        int g2 = l >> 2, t2 = l & 3;
        int n  = u * 8 + g2;
        int k0 = ks * 8 + t2;
        float f0 = (n < Ocols) ? W[k0 * Ocols + n] : 0.f;
        float f1 = (n < Ocols) ? W[(k0 + 4) * Ocols + n] : 0.f;
        uint32_t h0b = f2tf32(f0);
        uint32_t h1b = f2tf32(f1);
        uint32_t l0b = f2tf32(f0 - __uint_as_float(h0b));
        uint32_t l1b = f2tf32(f1 - __uint_as_float(h1b));
        Bs[idx] = make_uint4(h0b, h1b, l0b, l1b);
    }

    float4 acc[2][4];
    #pragma unroll
    for (int i = 0; i < 2; i++)
        #pragma unroll
        for (int j = 0; j < 4; j++) acc[i][j] = make_float4(0.f, 0.f, 0.f, 0.f);

    const int KQ = F / 4;
    for (int ks = 0; ks < F; ks += 32) {
        __syncthreads();   // As reuse guard (first pass: also publishes Bs/sa/sb)
        // stage 32 k-slices of X in fragment order
        for (int li = tid; li < 1024; li += 256) {
            int m  = li >> 3;           // row in tile 0..127
            int kq = li & 7;            // float4 index within the 32-k stage
            int row = node0 + m;
            if (row >= N_NODES) row = N_NODES - 1;   // clamp; stores guarded later
            float4 g = reinterpret_cast<const float4*>(X)[row * KQ + (ks >> 2) + kq];
            int t = m >> 4, r = m & 15, g2 = r & 7, half = r >> 3;
            #pragma unroll
            for (int j = 0; j < 4; j++) {
                int lk  = kq * 4 + j;        // 0..31
                int kst = lk >> 3;           // kstep-in-stage 0..3
                int c   = lk & 7;
                int s   = half + 2 * (c >> 2);
                As[((kst * 8 + t) * 32 + (g2 * 4 + (c & 3))) * 4 + s] = (&g.x)[j];
            }
        }
        __syncthreads();

        #pragma unroll
        for (int ksl = 0; ksl < 4; ksl++) {
            uint32_t ah[2][4], al[2][4];
            #pragma unroll
            for (int mt = 0; mt < 2; mt++) {
                float4 a = reinterpret_cast<float4*>(As)[(ksl * 8 + mw + mt) * 32 + lane];
                #pragma unroll
                for (int j = 0; j < 4; j++) {
                    float f = (&a.x)[j];
                    uint32_t hb = f2tf32(f);
                    ah[mt][j] = hb;
                    al[mt][j] = f2tf32(f - __uint_as_float(hb));
                }
            }
            int ksa = (ks >> 3) + ksl;
            #pragma unroll
            for (int nt = 0; nt < 4; nt++) {
                uint4 bb = Bs[(ksa * 8 + nh * 4 + nt) * 32 + lane];
                #pragma unroll
                for (int mt = 0; mt < 2; mt++) {
                    mma_tf32(acc[mt][nt], ah[mt][0], ah[mt][1], ah[mt][2], ah[mt][3], bb.x, bb.y);
                    mma_tf32(acc[mt][nt], ah[mt][0], ah[mt][1], ah[mt][2], ah[mt][3], bb.z, bb.w);
                    mma_tf32(acc[mt][nt], al[mt][0], al[mt][1], al[mt][2], al[mt][3], bb.x, bb.y);
                }
            }
        }
    }

    // epilogue: H store + fused attention dots
    float psr[2][2] = {{0.f, 0.f}, {0.f, 0.f}};
    float pdr[2][2] = {{0.f, 0.f}, {0.f, 0.f}};
    #pragma unroll
    for (int mt = 0; mt < 2; mt++) {
        int r0 = node0 + (w & 3) * 32 + mt * 16 + gid;
        int r1 = r0 + 8;
        #pragma unroll
        for (int nt = 0; nt < 4; nt++) {
            int nc = nh * 32 + nt * 8 + tig * 2;
            float4 d = acc[mt][nt];
            float s0 = sa[nc], s1 = sa[nc + 1];
            float t0 = sb[nc], t1 = sb[nc + 1];
            psr[mt][0] += d.x * s0 + d.y * s1;
            psr[mt][1] += d.z * s0 + d.w * s1;
            pdr[mt][0] += d.x * t0 + d.y * t1;
            pdr[mt][1] += d.z * t0 + d.w * t1;
            if (r0 < N_NODES) *reinterpret_cast<float2*>(&H[r0 * 64 + nc]) = make_float2(d.x, d.y);
            if (r1 < N_NODES) *reinterpret_cast<float2*>(&H[r1 * 64 + nc]) = make_float2(d.z, d.w);
        }
    }
    // reduce over tig (lanes gid*4+tig, xor 1 and 2 mix tig only)
    #pragma unroll
    for (int o = 1; o <= 2; o <<= 1) {
        #pragma unroll
        for (int mt = 0; mt < 2; mt++) {
            psr[mt][0] += __shfl_xor_sync(0xffffffffu, psr[mt][0], o);
            psr[mt][1] += __shfl_xor_sync(0xffffffffu, psr[mt][1], o);
            pdr[mt][0] += __shfl_xor_sync(0xffffffffu, pdr[mt][0], o);
            pdr[mt][1] += __shfl_xor_sync(0xffffffffu, pdr[mt][1], o);
        }
    }
    if (tig == 0) {
        #pragma unroll
        for (int mt = 0; mt < 2; mt++) {
            #pragma unroll
            for (int half = 0; half < 2; half++) {
                int rb = (w & 3) * 32 + mt * 16 + gid + half * 8;
                sps[nh * 128 + rb] = psr[mt][half];
                spd[nh * 128 + rb] = pdr[mt][half];
            }
        }
    }
    __syncthreads();
    if (tid < 128) {
        int row = node0 + tid;
        if (row < N_NODES) {
            g_ssrc[row] = sps[tid] + sps[128 + tid];
            g_sdst[row] = spd[tid] + spd[128 + tid];
        }
    }
}

// ---------------- fused edge softmax + aggregation: one warp per dst node -------
template <int OCOLS, bool GELU>
__global__ void k_edge(const float* __restrict__ H, const float* __restrict__ bias,
                       float* __restrict__ OUT) {
    int gw   = (blockIdx.x * blockDim.x + threadIdx.x) >> 5;
    int lane = threadIdx.x & 31;
    if (gw >= N_NODES) return;
    int s = g_off[gw], e = g_end[gw];
    float sd = g_sdst[gw];

    const int f0 = 2 * lane;
    const bool active = (OCOLS == 64) || (f0 < OCOLS);
    float sum = 0.f, a0 = 0.f, a1 = 0.f;
    for (int i0 = s; i0 < e; i0 += 32) {
        int i = i0 + lane;
        float ex = 0.f;
        int u = 0;
        if (i < e) {
            u = g_csrc[i];
            float sc = g_ssrc[u] + sd;
            sc = sc > 0.f ? sc : 0.2f * sc;      // leaky relu, slope 0.2
            ex = __expf(sc);                      // max-shift cancels; scores bounded
            sum += ex;
        }
        int cnt = min(32, e - i0);
        #pragma unroll 4
        for (int j = 0; j < cnt; j++) {
            float al = __shfl_sync(0xffffffffu, ex, j);
            int   us = __shfl_sync(0xffffffffu, u, j);
            if (active) {
                float2 hv = *reinterpret_cast<const float2*>(&H[us * 64 + f0]);
                a0 += al * hv.x;
                a1 += al * hv.y;
            }
        }
    }
    #pragma unroll
    for (int o = 16; o; o >>= 1) sum += __shfl_xor_sync(0xffffffffu, sum, o);
    float inv = 1.f / (sum + 1e-16f);

    if (active) {
        float v0 = a0 * inv + bias[f0];
        float v1 = a1 * inv + bias[f0 + 1];
        if (GELU) {
            v0 = 0.5f * v0 * (1.f + erff(v0 * 0.70710678118f));
            v1 = 0.5f * v1 * (1.f + erff(v1 * 0.70710678118f));
        }
        OUT[gw * OCOLS + f0]     = v0;
        OUT[gw * OCOLS + f0 + 1] = v1;
    }
}

// ---------------- launch ----------------
extern "C" void kernel_launch(void* const* d_in, const int* in_sizes, int n_in,
                              void* d_out, int out_size) {
    const float* x   = (const float*)d_in[0];
    const int*   ei  = (const int*)d_in[1];
    const float* W1  = (const float*)d_in[2];
    const float* as1 = (const float*)d_in[3];
    const float* ad1 = (const float*)d_in[4];
    const float* b1  = (const float*)d_in[5];
    const float* W2  = (const float*)d_in[6];
    const float* as2 = (const float*)d_in[7];
    const float* ad2 = (const float*)d_in[8];
    const float* b2  = (const float*)d_in[9];
    const float* W3  = (const float*)d_in[10];
    const float* as3 = (const float*)d_in[11];
    const float* ad3 = (const float*)d_in[12];
    const float* b3  = (const float*)d_in[13];
    float* out = (float*)d_out;

    float *h0, *h1;
    cudaGetSymbolAddress((void**)&h0, g_h0);
    cudaGetSymbolAddress((void**)&h1, g_h1);

    // smem floats: Bs F*128 + As 4096 + sa/sb 128 + sps/spd 512
    const size_t smem128 = (size_t)(128 * 128 + 4096 + 128 + 512) * 4;  // 84480
    const size_t smem64  = (size_t)(64 * 128 + 4096 + 128 + 512) * 4;   // 51712
    cudaFuncSetAttribute((const void*)k_gemm_tc<128>, cudaFuncAttributeMaxDynamicSharedMemorySize, (int)smem128);
    cudaFuncSetAttribute((const void*)k_gemm_tc<64>,  cudaFuncAttributeMaxDynamicSharedMemorySize, (int)smem64);

    // CSR build
    k_hist<<<(E_EDGES / 4 + 255) / 256, 256>>>(ei);
    k_offsets<<<(N_NODES + 1023) / 1024, 1024>>>();
    k_fill<<<(E_EDGES / 4 + N_NODES + 255) / 256, 256>>>(ei);

    const int gemm_grid = (N_NODES + 127) / 128;        // 391
    const int edge_grid = (N_NODES * 32 + 255) / 256;   // 6250

    // layer 1
    k_gemm_tc<128><<<gemm_grid, 256, smem128>>>(x, W1, HID, as1, ad1, h0);
    k_edge<HID, true><<<edge_grid, 256>>>(h0, b1, h1);
    // layer 2
    k_gemm_tc<64><<<gemm_grid, 256, smem64>>>(h1, W2, HID, as2, ad2, h0);
    k_edge<HID, true><<<edge_grid, 256>>>(h0, b2, h1);
    // layer 3 (O=40, padded to 64 internally)
    k_gemm_tc<64><<<gemm_grid, 256, smem64>>>(h1, W3, CLS, as3, ad3, h0);
    k_edge<CLS, false><<<edge_grid, 256>>>(h0, b3, out);
}

// round 9
// speedup vs baseline: 1.4433x; 1.4433x over previous
#include <cuda_runtime.h>
#include <cuda_fp16.h>
#include <math.h>
#include <stdint.h>

#define N_NODES 50000
#define E_EDGES 800000
#define E_TOT   850000   // edges + self loops
#define HID 64
#define CLS 40

// ---------------- scratch (__device__ globals: allocation-free) ----------------
__device__ __half2 g_h16[N_NODES * 32];   // GEMM output (fp16), gathered by edge kernel
__device__ float   g_hf[N_NODES * HID];   // edge output (fp32), GEMM input next layer
__device__ float   g_ssrc[N_NODES];
__device__ float   g_sdst[N_NODES];
__device__ int     g_cnt[N_NODES];        // zero-init; re-zeroed by k_offsets each call
__device__ int     g_off[N_NODES];
__device__ int     g_end[N_NODES];
__device__ int     g_cur[N_NODES];
__device__ int     g_csrc[E_TOT];
__device__ int     g_cursor;              // re-zeroed by k_hist each call

// ---------------- CSR build ----------------
__global__ void k_hist(const int* __restrict__ ei) {
    int i4 = blockIdx.x * blockDim.x + threadIdx.x;
    if (i4 == 0) g_cursor = 0;
    if (i4 < E_EDGES / 4) {
        int4 d = reinterpret_cast<const int4*>(ei + E_EDGES)[i4];
        if ((unsigned)d.x < N_NODES) atomicAdd(&g_cnt[d.x], 1);
        if ((unsigned)d.y < N_NODES) atomicAdd(&g_cnt[d.y], 1);
        if ((unsigned)d.z < N_NODES) atomicAdd(&g_cnt[d.z], 1);
        if ((unsigned)d.w < N_NODES) atomicAdd(&g_cnt[d.w], 1);
    }
}

// warp-aggregated atomic segment allocation (CSR valid regardless of segment order)
__global__ void k_offsets() {
    int idx  = blockIdx.x * blockDim.x + threadIdx.x;
    int lane = threadIdx.x & 31;
    int v = 0;
    if (idx < N_NODES) { v = g_cnt[idx] + 1; g_cnt[idx] = 0; }  // +1 self loop; re-zero
    int incl = v;
    #pragma unroll
    for (int s = 1; s < 32; s <<= 1) {
        int t = __shfl_up_sync(0xffffffffu, incl, s);
        if (lane >= s) incl += t;
    }
    int tot = __shfl_sync(0xffffffffu, incl, 31);
    int base = 0;
    if (lane == 0) base = atomicAdd(&g_cursor, tot);
    base = __shfl_sync(0xffffffffu, base, 0);
    if (idx < N_NODES) {
        int excl = base + incl - v;
        g_off[idx] = excl;
        g_cur[idx] = excl;
        g_end[idx] = excl + v;
    }
}

__global__ void k_fill(const int* __restrict__ ei) {
    int i4 = blockIdx.x * blockDim.x + threadIdx.x;
    const int Q = E_EDGES / 4;
    if (i4 < Q) {
        int4 s = reinterpret_cast<const int4*>(ei)[i4];
        int4 d = reinterpret_cast<const int4*>(ei + E_EDGES)[i4];
        if ((unsigned)d.x < N_NODES && (unsigned)s.x < N_NODES) g_csrc[atomicAdd(&g_cur[d.x], 1)] = s.x;
        if ((unsigned)d.y < N_NODES && (unsigned)s.y < N_NODES) g_csrc[atomicAdd(&g_cur[d.y], 1)] = s.y;
        if ((unsigned)d.z < N_NODES && (unsigned)s.z < N_NODES) g_csrc[atomicAdd(&g_cur[d.z], 1)] = s.z;
        if ((unsigned)d.w < N_NODES && (unsigned)s.w < N_NODES) g_csrc[atomicAdd(&g_cur[d.w], 1)] = s.w;
    } else {
        int id = i4 - Q;
        if (id < N_NODES) g_csrc[atomicAdd(&g_cur[id], 1)] = id;  // self loop
    }
}

// ---------------- fused GEMM: H = X@W (stored fp16), s_src/s_dst fused (fp32) -----
// 128 rows x 64 cols per block, 256 threads, 8x4 microtile; A tile K-staged (KS).
template <int F, int KS>
__global__ void __launch_bounds__(256, 4)
k_gemm(const float* __restrict__ X, const float* __restrict__ W,
       int Ocols,
       const float* __restrict__ asrc, const float* __restrict__ adst,
       __half2* __restrict__ H) {
    extern __shared__ float sm[];
    float* As = sm;               // [KS][132]  (k-major, padded; 132*4 % 16 == 0)
    float* Bs = As + KS * 132;    // [F][64]    (full W tile)
    float* sa = Bs + F * 64;      // [64]
    float* sb = sa + 64;          // [64]
    const int tid = threadIdx.x;
    const int node0 = blockIdx.x * 128;
    const int KQ = F / 4;

    if (tid < 64) {
        sa[tid] = (tid < Ocols) ? asrc[tid] : 0.f;
        sb[tid] = (tid < Ocols) ? adst[tid] : 0.f;
    }
    for (int idx = tid; idx < F * 64; idx += 256) {
        int k = idx >> 6, n = idx & 63;
        Bs[idx] = (n < Ocols) ? W[k * Ocols + n] : 0.f;
    }

    const int n0 = (tid & 15) * 4;
    const int m0 = (tid >> 4) * 8;
    float acc[8][4];
    #pragma unroll
    for (int i = 0; i < 8; i++)
        #pragma unroll
        for (int j = 0; j < 4; j++) acc[i][j] = 0.f;

    for (int ks = 0; ks < F; ks += KS) {
        __syncthreads();   // As reuse guard (also orders Bs/sa/sb on first pass)
        constexpr int KSQ = KS / 4;
        for (int li = tid; li < 128 * KSQ; li += 256) {
            int m = li / KSQ, kq = li % KSQ;
            int row = node0 + m;
            if (row >= N_NODES) row = N_NODES - 1;   // clamp; stores guarded below
            float4 g = reinterpret_cast<const float4*>(X)[row * KQ + (ks >> 2) + kq];
            int k = kq * 4;
            As[(k + 0) * 132 + m] = g.x;
            As[(k + 1) * 132 + m] = g.y;
            As[(k + 2) * 132 + m] = g.z;
            As[(k + 3) * 132 + m] = g.w;
        }
        __syncthreads();

        #pragma unroll 4
        for (int kk = 0; kk < KS; kk++) {
            float4 b  = *reinterpret_cast<const float4*>(&Bs[(ks + kk) * 64 + n0]);
            float4 al = *reinterpret_cast<const float4*>(&As[kk * 132 + m0]);
            float4 ah = *reinterpret_cast<const float4*>(&As[kk * 132 + m0 + 4]);
            acc[0][0] += al.x * b.x; acc[0][1] += al.x * b.y; acc[0][2] += al.x * b.z; acc[0][3] += al.x * b.w;
            acc[1][0] += al.y * b.x; acc[1][1] += al.y * b.y; acc[1][2] += al.y * b.z; acc[1][3] += al.y * b.w;
            acc[2][0] += al.z * b.x; acc[2][1] += al.z * b.y; acc[2][2] += al.z * b.z; acc[2][3] += al.z * b.w;
            acc[3][0] += al.w * b.x; acc[3][1] += al.w * b.y; acc[3][2] += al.w * b.z; acc[3][3] += al.w * b.w;
            acc[4][0] += ah.x * b.x; acc[4][1] += ah.x * b.y; acc[4][2] += ah.x * b.z; acc[4][3] += ah.x * b.w;
            acc[5][0] += ah.y * b.x; acc[5][1] += ah.y * b.y; acc[5][2] += ah.y * b.z; acc[5][3] += ah.y * b.w;
            acc[6][0] += ah.z * b.x; acc[6][1] += ah.z * b.y; acc[6][2] += ah.z * b.z; acc[6][3] += ah.z * b.w;
            acc[7][0] += ah.w * b.x; acc[7][1] += ah.w * b.y; acc[7][2] += ah.w * b.z; acc[7][3] += ah.w * b.w;
        }
    }

    #pragma unroll
    for (int i = 0; i < 8; i++) {
        int row = node0 + m0 + i;
        float ps = acc[i][0] * sa[n0]     + acc[i][1] * sa[n0 + 1]
                 + acc[i][2] * sa[n0 + 2] + acc[i][3] * sa[n0 + 3];
        float pd = acc[i][0] * sb[n0]     + acc[i][1] * sb[n0 + 1]
                 + acc[i][2] * sb[n0 + 2] + acc[i][3] * sb[n0 + 3];
        #pragma unroll
        for (int o = 1; o < 16; o <<= 1) {
            ps += __shfl_xor_sync(0xffffffffu, ps, o);
            pd += __shfl_xor_sync(0xffffffffu, pd, o);
        }
        if (row < N_NODES) {
            // fp16 store: 2x half2 = 8B per thread (scores above use fp32 accs)
            __half2 h01 = __floats2half2_rn(acc[i][0], acc[i][1]);
            __half2 h23 = __floats2half2_rn(acc[i][2], acc[i][3]);
            uint2 pk;
            pk.x = *reinterpret_cast<uint32_t*>(&h01);
            pk.y = *reinterpret_cast<uint32_t*>(&h23);
            *reinterpret_cast<uint2*>(&H[row * 32 + (n0 >> 1)]) = pk;
            if ((tid & 15) == 0) { g_ssrc[row] = ps; g_sdst[row] = pd; }
        }
    }
}

// ---------------- fused edge softmax + aggregation: one warp per dst node -------
// Gathers fp16 H (half2 per lane = 4B), accumulates fp32.
template <int OCOLS, bool GELU>
__global__ void k_edge(const __half2* __restrict__ H, const float* __restrict__ bias,
                       float* __restrict__ OUT) {
    int gw   = (blockIdx.x * blockDim.x + threadIdx.x) >> 5;
    int lane = threadIdx.x & 31;
    if (gw >= N_NODES) return;
    int s = g_off[gw], e = g_end[gw];
    float sd = g_sdst[gw];

    const int f0 = 2 * lane;
    const bool active = (OCOLS == 64) || (f0 < OCOLS);
    float sum = 0.f, a0 = 0.f, a1 = 0.f;
    for (int i0 = s; i0 < e; i0 += 32) {
        int i = i0 + lane;
        float ex = 0.f;
        int u = 0;
        if (i < e) {
            u = g_csrc[i];
            float sc = g_ssrc[u] + sd;
            sc = sc > 0.f ? sc : 0.2f * sc;      // leaky relu, slope 0.2
            ex = __expf(sc);                      // max-shift cancels; scores bounded
            sum += ex;
        }
        int cnt = min(32, e - i0);
        #pragma unroll 4
        for (int j = 0; j < cnt; j++) {
            float al = __shfl_sync(0xffffffffu, ex, j);
            int   us = __shfl_sync(0xffffffffu, u, j);
            if (active) {
                float2 hv = __half22float2(H[us * 32 + lane]);
                a0 += al * hv.x;
                a1 += al * hv.y;
            }
        }
    }
    #pragma unroll
    for (int o = 16; o; o >>= 1) sum += __shfl_xor_sync(0xffffffffu, sum, o);
    float inv = 1.f / (sum + 1e-16f);

    if (active) {
        float v0 = a0 * inv + bias[f0];
        float v1 = a1 * inv + bias[f0 + 1];
        if (GELU) {
            v0 = 0.5f * v0 * (1.f + erff(v0 * 0.70710678118f));
            v1 = 0.5f * v1 * (1.f + erff(v1 * 0.70710678118f));
        }
        OUT[gw * OCOLS + f0]     = v0;
        OUT[gw * OCOLS + f0 + 1] = v1;
    }
}

// ---------------- launch ----------------
extern "C" void kernel_launch(void* const* d_in, const int* in_sizes, int n_in,
                              void* d_out, int out_size) {
    const float* x   = (const float*)d_in[0];
    const int*   ei  = (const int*)d_in[1];
    const float* W1  = (const float*)d_in[2];
    const float* as1 = (const float*)d_in[3];
    const float* ad1 = (const float*)d_in[4];
    const float* b1  = (const float*)d_in[5];
    const float* W2  = (const float*)d_in[6];
    const float* as2 = (const float*)d_in[7];
    const float* ad2 = (const float*)d_in[8];
    const float* b2  = (const float*)d_in[9];
    const float* W3  = (const float*)d_in[10];
    const float* as3 = (const float*)d_in[11];
    const float* ad3 = (const float*)d_in[12];
    const float* b3  = (const float*)d_in[13];
    float* out = (float*)d_out;

    __half2* h16;
    float*   hf;
    cudaGetSymbolAddress((void**)&h16, g_h16);
    cudaGetSymbolAddress((void**)&hf,  g_hf);

    // smem: As KS*132 + Bs F*64 + 128
    const size_t smem128 = (size_t)(32 * 132 + 128 * 64 + 128) * 4;  // 50176
    const size_t smem64  = (size_t)(32 * 132 + 64 * 64 + 128) * 4;   // 33792
    cudaFuncSetAttribute((const void*)k_gemm<128, 32>, cudaFuncAttributeMaxDynamicSharedMemorySize, (int)smem128);
    cudaFuncSetAttribute((const void*)k_gemm<64, 32>,  cudaFuncAttributeMaxDynamicSharedMemorySize, (int)smem64);

    // CSR build
    k_hist<<<(E_EDGES / 4 + 255) / 256, 256>>>(ei);
    k_offsets<<<(N_NODES + 1023) / 1024, 1024>>>();
    k_fill<<<(E_EDGES / 4 + N_NODES + 255) / 256, 256>>>(ei);

    const int gemm_grid = (N_NODES + 127) / 128;        // 391
    const int edge_grid = (N_NODES * 32 + 255) / 256;   // 6250

    // layer 1
    k_gemm<128, 32><<<gemm_grid, 256, smem128>>>(x, W1, HID, as1, ad1, h16);
    k_edge<HID, true><<<edge_grid, 256>>>(h16, b1, hf);
    // layer 2
    k_gemm<64, 32><<<gemm_grid, 256, smem64>>>(hf, W2, HID, as2, ad2, h16);
    k_edge<HID, true><<<edge_grid, 256>>>(h16, b2, hf);
    // layer 3 (O=40, padded to 64 internally)
    k_gemm<64, 32><<<gemm_grid, 256, smem64>>>(hf, W3, CLS, as3, ad3, h16);
    k_edge<CLS, false><<<edge_grid, 256>>>(h16, b3, out);
}